// round 12
// baseline (speedup 1.0000x reference)
#include <cuda_runtime.h>
#include <cuda_bf16.h>
#include <math.h>

#define TOK   16384      // B*S = 4*4096
#define DIN   2048
#define HIDN  256
#define NHEAD 16
#define HDIM  128
#define KSEL  4
#define OUTW  (KSEL*HDIM)   // 512

// ---- device scratch (no allocations allowed) ----
__device__ float g_prob[TOK * KSEL];     // gate prob per (token, slot)
__device__ int   g_list[NHEAD * TOK];    // per-head token*4+slot lists
__device__ int   g_cnt[NHEAD];           // per-head counts
__device__ float g_cnorm[NHEAD * HIDN];  // normalized centroids
__device__ float g_d[NHEAD * DIN];       // d_n = Wr^T c_norm_n  [16][2048]
__device__ float g_n2p[4][TOK];          // ||z||^2 partials (deterministic)
__device__ int   g_flag[TOK];            // flagged (ambiguous) tokens
__device__ int   g_nflag;                // count
__device__ float g_xt[(size_t)TOK * DIN];          // tf32-rounded X (128MB)
__device__ float g_wt[(size_t)NHEAD * HDIM * DIN]; // tf32-rounded W (16MB)

// ---- mma helpers ----
__device__ __forceinline__ unsigned f2tf32(float x) {
    unsigned r;
    asm("cvt.rna.tf32.f32 %0, %1;" : "=r"(r) : "f"(x));
    return r;
}
__device__ __forceinline__ void mma_tf32(float* c, const unsigned* a, const unsigned* b) {
    asm volatile(
        "mma.sync.aligned.m16n8k8.row.col.f32.tf32.tf32.f32 "
        "{%0,%1,%2,%3}, {%4,%5,%6,%7}, {%8,%9}, {%0,%1,%2,%3};"
        : "+f"(c[0]), "+f"(c[1]), "+f"(c[2]), "+f"(c[3])
        : "r"(a[0]), "r"(a[1]), "r"(a[2]), "r"(a[3]), "r"(b[0]), "r"(b[1]));
}
__device__ __forceinline__ void mma_bf16(float* c, const unsigned* a, const unsigned* b) {
    asm volatile(
        "mma.sync.aligned.m16n8k16.row.col.f32.bf16.bf16.f32 "
        "{%0,%1,%2,%3}, {%4,%5,%6,%7}, {%8,%9}, {%0,%1,%2,%3};"
        : "+f"(c[0]), "+f"(c[1]), "+f"(c[2]), "+f"(c[3])
        : "r"(a[0]), "r"(a[1]), "r"(a[2]), "r"(a[3]), "r"(b[0]), "r"(b[1]));
}
__device__ __forceinline__ unsigned pack_bf16(float x, float y) {
    __nv_bfloat162 p = __floats2bfloat162_rn(x, y);
    return *reinterpret_cast<unsigned*>(&p);
}
__device__ __forceinline__ void cp16(unsigned smem_byte_addr, const void* gptr) {
    asm volatile("cp.async.cg.shared.global [%0], [%1], 16;"
                 :: "r"(smem_byte_addr), "l"(gptr));
}

// ============================================================
// Kernel 0: zero counters + normalize centroids
// ============================================================
__global__ void prep_kernel(const float* __restrict__ cent) {
    int tid = threadIdx.x;
    if (tid < NHEAD) g_cnt[tid] = 0;
    if (tid == 0) g_nflag = 0;
    int w = tid >> 5, lane = tid & 31;
    for (int n = w; n < NHEAD; n += 8) {
        float s = 0.f;
        for (int i = lane; i < HIDN; i += 32) {
            float v = cent[n * HIDN + i];
            s += v * v;
        }
        #pragma unroll
        for (int o = 16; o; o >>= 1) s += __shfl_xor_sync(0xffffffffu, s, o);
        float inv = 1.0f / fmaxf(sqrtf(s), 1e-12f);
        for (int i = lane; i < HIDN; i += 32)
            g_cnorm[n * HIDN + i] = cent[n * HIDN + i] * inv;
    }
}

// ============================================================
// Kernel 1: d[n][k] = sum_h c_norm[n][h] * Wr[h][k]   (fp32 exact)
// ============================================================
__global__ void dprep_kernel(const float* __restrict__ Wr) {
    __shared__ float cn[16][256];
    __shared__ float Ws[32][128];
    int tid = threadIdx.x;
    int kbase = blockIdx.x * 128;
    for (int i = tid; i < 16 * 256; i += 256) cn[i >> 8][i & 255] = g_cnorm[i];
    int kk = tid & 127, grp = tid >> 7;
    float acc[8] = {0.f, 0.f, 0.f, 0.f, 0.f, 0.f, 0.f, 0.f};
    for (int hc = 0; hc < 256; hc += 32) {
        __syncthreads();
        for (int i = tid; i < 32 * 128; i += 256) {
            int r = i >> 7, c = i & 127;
            Ws[r][c] = Wr[(size_t)(hc + r) * DIN + kbase + c];
        }
        __syncthreads();
        #pragma unroll 8
        for (int hh = 0; hh < 32; hh++) {
            float wv = Ws[hh][kk];
            #pragma unroll
            for (int i = 0; i < 8; i++)
                acc[i] += cn[grp * 8 + i][hc + hh] * wv;
        }
    }
    #pragma unroll
    for (int i = 0; i < 8; i++)
        g_d[(grp * 8 + i) * DIN + kbase + kk] = acc[i];
}

// ============================================================
// Kernel 1b: pre-round W to tf32 (cp.async raw bytes = rna-rounded)
// ============================================================
__global__ void wprep_kernel(const float* __restrict__ W) {
    size_t i = (size_t)blockIdx.x * 256 + threadIdx.x;   // float4 index
    float4 v = *(const float4*)(W + i * 4);
    uint4 u;
    u.x = f2tf32(v.x); u.y = f2tf32(v.y);
    u.z = f2tf32(v.z); u.w = f2tf32(v.w);
    *(uint4*)(g_wt + i * 4) = u;
}

// ============================================================
// Kernel 2: ||z||^2 via bf16 mma (2-stage pipelined) + fused
// X -> tf32 pre-rounding STG (n0==0 CTAs only).
// ============================================================
__global__ __launch_bounds__(256, 2) void zn_kernel(
    const float* __restrict__ X, const float* __restrict__ Wr) {
    __shared__ unsigned As[2][128][12];
    __shared__ unsigned Bs[2][128][12];

    int tid = threadIdx.x;
    int m0 = blockIdx.y * 128;
    int n0 = blockIdx.x * 128;
    bool wrx = (blockIdx.x == 0);
    int wid = tid >> 5, lane = tid & 31;
    int wm = wid >> 1, wn = wid & 1;
    int g = lane >> 2, t = lane & 3;

    const float* aptr[2];
    const float* bptr[2];
    float* xtp[2];
    int rowL[2], c4L[2];
    #pragma unroll
    for (int i = 0; i < 2; i++) {
        int idx = tid + i * 256;
        rowL[i] = idx >> 2;
        c4L[i] = idx & 3;
        aptr[i] = X  + (size_t)(m0 + rowL[i]) * DIN + c4L[i] * 4;
        bptr[i] = Wr + (size_t)(n0 + rowL[i]) * DIN + c4L[i] * 4;
        xtp[i]  = g_xt + (size_t)(m0 + rowL[i]) * DIN + c4L[i] * 4;
    }

    float acc[2][8][4];
    #pragma unroll
    for (int i = 0; i < 2; i++)
        #pragma unroll
        for (int j = 0; j < 8; j++)
            #pragma unroll
            for (int q = 0; q < 4; q++) acc[i][j][q] = 0.f;

    float4 av[2], bv[2];
    #pragma unroll
    for (int i = 0; i < 2; i++) {
        av[i] = *(const float4*)aptr[i];
        bv[i] = *(const float4*)bptr[i];
    }
    #pragma unroll
    for (int i = 0; i < 2; i++) {
        As[0][rowL[i]][c4L[i] * 2 + 0] = pack_bf16(av[i].x, av[i].y);
        As[0][rowL[i]][c4L[i] * 2 + 1] = pack_bf16(av[i].z, av[i].w);
        Bs[0][rowL[i]][c4L[i] * 2 + 0] = pack_bf16(bv[i].x, bv[i].y);
        Bs[0][rowL[i]][c4L[i] * 2 + 1] = pack_bf16(bv[i].z, bv[i].w);
        if (wrx) {
            uint4 u;
            u.x = f2tf32(av[i].x); u.y = f2tf32(av[i].y);
            u.z = f2tf32(av[i].z); u.w = f2tf32(av[i].w);
            *(uint4*)xtp[i] = u;
        }
    }
    __syncthreads();

    int cur = 0;
    for (int k0 = 0; k0 < DIN; k0 += 16) {
        bool nxt = (k0 + 16) < DIN;
        if (nxt) {
            #pragma unroll
            for (int i = 0; i < 2; i++) {
                av[i] = *(const float4*)(aptr[i] + k0 + 16);
                bv[i] = *(const float4*)(bptr[i] + k0 + 16);
            }
        }
        {
            unsigned a[2][4], b[8][2];
            #pragma unroll
            for (int mt = 0; mt < 2; mt++) {
                int rm = wm * 32 + mt * 16 + g;
                a[mt][0] = As[cur][rm][t];
                a[mt][1] = As[cur][rm + 8][t];
                a[mt][2] = As[cur][rm][t + 4];
                a[mt][3] = As[cur][rm + 8][t + 4];
            }
            #pragma unroll
            for (int nt = 0; nt < 8; nt++) {
                int rn = wn * 64 + nt * 8 + g;
                b[nt][0] = Bs[cur][rn][t];
                b[nt][1] = Bs[cur][rn][t + 4];
            }
            #pragma unroll
            for (int mt = 0; mt < 2; mt++)
                #pragma unroll
                for (int nt = 0; nt < 8; nt++)
                    mma_bf16(acc[mt][nt], a[mt], b[nt]);
        }
        if (nxt) {
            int st = cur ^ 1;
            #pragma unroll
            for (int i = 0; i < 2; i++) {
                As[st][rowL[i]][c4L[i] * 2 + 0] = pack_bf16(av[i].x, av[i].y);
                As[st][rowL[i]][c4L[i] * 2 + 1] = pack_bf16(av[i].z, av[i].w);
                Bs[st][rowL[i]][c4L[i] * 2 + 0] = pack_bf16(bv[i].x, bv[i].y);
                Bs[st][rowL[i]][c4L[i] * 2 + 1] = pack_bf16(bv[i].z, bv[i].w);
                if (wrx) {
                    uint4 u;
                    u.x = f2tf32(av[i].x); u.y = f2tf32(av[i].y);
                    u.z = f2tf32(av[i].z); u.w = f2tf32(av[i].w);
                    *(uint4*)(xtp[i] + k0 + 16) = u;
                }
            }
        }
        __syncthreads();
        cur ^= 1;
    }

    int p = blockIdx.x * 2 + wn;
    #pragma unroll
    for (int mt = 0; mt < 2; mt++) {
        float s0 = 0.f, s1 = 0.f;
        #pragma unroll
        for (int nt = 0; nt < 8; nt++) {
            s0 += acc[mt][nt][0] * acc[mt][nt][0] + acc[mt][nt][1] * acc[mt][nt][1];
            s1 += acc[mt][nt][2] * acc[mt][nt][2] + acc[mt][nt][3] * acc[mt][nt][3];
        }
        s0 += __shfl_xor_sync(0xffffffffu, s0, 1);
        s0 += __shfl_xor_sync(0xffffffffu, s0, 2);
        s1 += __shfl_xor_sync(0xffffffffu, s1, 1);
        s1 += __shfl_xor_sync(0xffffffffu, s1, 2);
        if (t == 0) {
            int r = m0 + wm * 32 + mt * 16 + g;
            g_n2p[p][r] = s0;
            g_n2p[p][r + 8] = s1;
        }
    }
}

// ============================================================
// Kernel 3: fast routing, 2 tokens per warp (VERBATIM R10 winner)
// ============================================================
__global__ __launch_bounds__(256) void lroute_fast(
    const float* __restrict__ X, const float* __restrict__ temp) {
    __shared__ float ds[16][512];
    int tid = threadIdx.x, lane = tid & 31, w = tid >> 5;
    int tbase = blockIdx.x * 16 + w * 2;
    const float* xr0 = X + (size_t)tbase * DIN;

    float acc[2][16];
    #pragma unroll
    for (int q = 0; q < 2; q++)
        #pragma unroll
        for (int n = 0; n < 16; n++) acc[q][n] = 0.f;

    for (int c = 0; c < 4; c++) {
        __syncthreads();
        for (int i = tid; i < 16 * 128; i += 256) {
            int n = i >> 7, j = i & 127;
            *(float4*)&ds[n][j * 4] = *(const float4*)&g_d[n * DIN + c * 512 + j * 4];
        }
        __syncthreads();
        #pragma unroll
        for (int it = 0; it < 4; it++) {
            int k4 = it * 32 + lane;
            float4 xv0 = *(const float4*)&xr0[c * 512 + k4 * 4];
            float4 xv1 = *(const float4*)&xr0[DIN + c * 512 + k4 * 4];
            #pragma unroll
            for (int n = 0; n < 16; n++) {
                float4 dv = *(const float4*)&ds[n][k4 * 4];
                acc[0][n] += xv0.x * dv.x + xv0.y * dv.y + xv0.z * dv.z + xv0.w * dv.w;
                acc[1][n] += xv1.x * dv.x + xv1.y * dv.y + xv1.z * dv.z + xv1.w * dv.w;
            }
        }
    }
    #pragma unroll
    for (int o = 16; o; o >>= 1)
        #pragma unroll
        for (int q = 0; q < 2; q++)
            #pragma unroll
            for (int n = 0; n < 16; n++)
                acc[q][n] += __shfl_xor_sync(0xffffffffu, acc[q][n], o);

    if (lane < 2) {
        int q = lane;
        int t = tbase + q;
        float u[16];
        #pragma unroll
        for (int n = 0; n < 16; n++) u[n] = acc[q][n];
        float S = 0.f;
        #pragma unroll
        for (int n = 0; n < 16; n++) S = fmaxf(S, fabsf(u[n]));
        float v5[5];
        int i5[5];
        bool used[16];
        #pragma unroll
        for (int n = 0; n < 16; n++) used[n] = false;
        #pragma unroll
        for (int r = 0; r < 5; r++) {
            int bi = 0;
            float bv = -1e30f;
            #pragma unroll
            for (int n = 0; n < 16; n++)
                if (!used[n] && u[n] > bv) { bv = u[n]; bi = n; }
            used[bi] = true;
            v5[r] = bv;
            i5[r] = bi;
        }
        float tau = 1e-4f * S + 1e-12f;
        bool safe = (v5[0] - v5[1] > tau) && (v5[1] - v5[2] > tau) &&
                    (v5[2] - v5[3] > tau) && (v5[3] - v5[4] > tau);
        if (!safe) {
            int p = atomicAdd(&g_nflag, 1);
            g_flag[p] = t;
        } else {
            float n2 = g_n2p[0][t] + g_n2p[1][t] + g_n2p[2][t] + g_n2p[3][t];
            float inv = 1.0f / fmaxf(sqrtf(n2), 1e-12f);
            float sc = inv * 0.0625f * expf(temp[0]);
            float lg[16];
            float mx = -1e30f;
            #pragma unroll
            for (int n = 0; n < 16; n++) {
                lg[n] = u[n] * sc;
                mx = fmaxf(mx, lg[n]);
            }
            float sum = 0.f;
            #pragma unroll
            for (int n = 0; n < 16; n++) {
                lg[n] = expf(lg[n] - mx);
                sum += lg[n];
            }
            float isum = 1.0f / sum;
            #pragma unroll
            for (int k = 0; k < KSEL; k++) {
                int bi = i5[k];
                g_prob[t * KSEL + k] = lg[bi] * isum;
                int pos = atomicAdd(&g_cnt[bi], 1);
                g_list[bi * TOK + pos] = (t << 2) | k;
            }
        }
    }
}

// ============================================================
// Kernel 4: exact fallback for flagged tokens (bit-identical R1 chain).
// ============================================================
__global__ __launch_bounds__(256) void fallback_kernel(
    const float* __restrict__ X, const float* __restrict__ Wr,
    const float* __restrict__ temp) {
    __shared__ float xs[DIN];
    __shared__ float Wt[256][36];
    __shared__ float zs[256];
    __shared__ float red[8];
    __shared__ float slog[16];

    int nf = g_nflag;
    int tid = threadIdx.x, lane = tid & 31, w = tid >> 5;

    for (int fi = blockIdx.x; fi < nf; fi += gridDim.x) {
        int t = g_flag[fi];
        for (int i = tid; i < DIN / 4; i += 256)
            *(float4*)&xs[i * 4] = *(const float4*)&X[(size_t)t * DIN + i * 4];
        __syncthreads();
        float acc = 0.f;
        for (int k0 = 0; k0 < DIN; k0 += 32) {
            __syncthreads();
            for (int i = tid; i < 256 * 8; i += 256) {
                int r = i >> 3, c4 = i & 7;
                *(float4*)&Wt[r][c4 * 4] =
                    *(const float4*)&Wr[(size_t)r * DIN + k0 + c4 * 4];
            }
            __syncthreads();
            #pragma unroll
            for (int kk = 0; kk < 32; kk++)
                acc = __fmaf_rn(xs[k0 + kk], Wt[tid][kk], acc);
        }
        __syncthreads();
        float z = acc;
        zs[tid] = z;
        float s = z * z;
        #pragma unroll
        for (int o = 16; o; o >>= 1) s += __shfl_xor_sync(0xffffffffu, s, o);
        if (lane == 0) red[w] = s;
        __syncthreads();
        float tot = 0.f;
        #pragma unroll
        for (int i = 0; i < 8; i++) tot += red[i];
        float inv = 1.0f / fmaxf(sqrtf(tot), 1e-12f);

        for (int n = w; n < NHEAD; n += 8) {
            float p = 0.f;
            for (int i = lane; i < HIDN; i += 32) p += zs[i] * g_cnorm[n * HIDN + i];
            #pragma unroll
            for (int o = 16; o; o >>= 1) p += __shfl_xor_sync(0xffffffffu, p, o);
            if (lane == 0) slog[n] = p;
        }
        __syncthreads();

        if (tid == 0) {
            float sc = inv * 0.0625f * expf(temp[0]);
            float lg[16];
            float mx = -1e30f;
            #pragma unroll
            for (int n = 0; n < NHEAD; n++) {
                lg[n] = slog[n] * sc;
                mx = fmaxf(mx, lg[n]);
            }
            float sum = 0.f;
            #pragma unroll
            for (int n = 0; n < NHEAD; n++) {
                lg[n] = expf(lg[n] - mx);
                sum += lg[n];
            }
            float isum = 1.0f / sum;
            bool used[16];
            #pragma unroll
            for (int n = 0; n < NHEAD; n++) used[n] = false;
            for (int k = 0; k < KSEL; k++) {
                int bi = 0;
                float bv = -1e30f;
                #pragma unroll
                for (int n = 0; n < NHEAD; n++) {
                    if (!used[n] && lg[n] > bv) { bv = lg[n]; bi = n; }
                }
                used[bi] = true;
                g_prob[t * KSEL + k] = bv * isum;
                int pos = atomicAdd(&g_cnt[bi], 1);
                g_list[bi * TOK + pos] = (t << 2) | k;
            }
        }
        __syncthreads();
    }
}

// ============================================================
// Kernel 5: grouped expert GEMM, tf32 mma, cp.async 2-stage BK=32
// (dynamic smem). 64 iters; one wait+sync per 4 mma phases.
// Stage layout: rows stride 36 words (16B-aligned, conflict-free).
// Operands pre-rounded -> bitwise identical accumulation.
// ============================================================
#define EXP_STRIDE 36
#define EXP_STAGE  (128 * EXP_STRIDE)          // words per stage per matrix
#define EXP_DYN_WORDS (4 * EXP_STAGE)          // A0,A1,B0,B1
#define EXP_DYN_BYTES (EXP_DYN_WORDS * 4)      // 73728 bytes

extern __shared__ unsigned exp_dsm[];

__global__ void gemm_expert_cp(
    const float* __restrict__ bias, float* __restrict__ out) {
    int h = blockIdx.y;
    int cnt = g_cnt[h];
    int base = blockIdx.x * 128;
    if (base >= cnt) return;

    unsigned* A0 = exp_dsm;                    // [2][128][36]
    unsigned* B0 = exp_dsm + 2 * EXP_STAGE;    // [2][128][36]
    __shared__ int   s_ent[128];
    __shared__ float s_prob[128];
    __shared__ float s_bias[128];

    int tid = threadIdx.x;
    if (tid < 128) {
        int r = base + tid;
        int rr = (r < cnt) ? r : (cnt - 1);
        int ent = g_list[h * TOK + rr];
        s_ent[tid] = ent;
        s_prob[tid] = g_prob[ent];
        s_bias[tid] = bias[h * HDIM + tid];
    }
    __syncthreads();

    // cp coords: 2 threads per row; each does 4 cp16 per matrix per tile.
    int row_c = tid >> 1;
    int ch = (tid & 1) * 16;                   // col half base (floats)
    const float* arow = g_xt + (size_t)(s_ent[row_c] >> 2) * DIN + ch;
    const float* brow = g_wt + (size_t)h * HDIM * DIN + (size_t)row_c * DIN + ch;
    unsigned sa = (unsigned)__cvta_generic_to_shared(A0);
    unsigned sb = (unsigned)__cvta_generic_to_shared(B0);
    unsigned doff = (unsigned)(row_c * EXP_STRIDE + ch) * 4;
    const unsigned stb = EXP_STAGE * 4;        // bytes per stage

    int wid = tid >> 5, lane = tid & 31;
    int wm = wid >> 1, wn = wid & 1;
    int g = lane >> 2, t = lane & 3;

    float acc[2][8][4];
    #pragma unroll
    for (int i = 0; i < 2; i++)
        #pragma unroll
        for (int j = 0; j < 8; j++)
            #pragma unroll
            for (int q = 0; q < 4; q++) acc[i][j][q] = 0.f;

    // prologue: tile 0 -> stage 0
    #pragma unroll
    for (int j = 0; j < 4; j++) {
        cp16(sa + doff + j * 16, arow + j * 4);
        cp16(sb + doff + j * 16, brow + j * 4);
    }
    asm volatile("cp.async.commit_group;");

    const int NIT = DIN / 32;   // 64
    for (int it = 0; it < NIT; it++) {
        asm volatile("cp.async.wait_group 0;");
        __syncthreads();
        int cur = it & 1;
        // issue next tile into other stage (overlaps the 4 mma phases below)
        if (it + 1 < NIT) {
            unsigned so = (unsigned)(cur ^ 1) * stb;
            const float* an = arow + (size_t)(it + 1) * 32;
            const float* bn = brow + (size_t)(it + 1) * 32;
            #pragma unroll
            for (int j = 0; j < 4; j++) {
                cp16(sa + so + doff + j * 16, an + j * 4);
                cp16(sb + so + doff + j * 16, bn + j * 4);
            }
        }
        asm volatile("cp.async.commit_group;");
        // 4 k8 phases from stage cur
        const unsigned* Ac = A0 + cur * EXP_STAGE;
        const unsigned* Bc = B0 + cur * EXP_STAGE;
        #pragma unroll
        for (int s = 0; s < 4; s++) {
            unsigned a[2][4], b[8][2];
            int kc = s * 8 + t;
            #pragma unroll
            for (int mt = 0; mt < 2; mt++) {
                int rm = wm * 32 + mt * 16 + g;
                a[mt][0] = Ac[rm * EXP_STRIDE + kc];
                a[mt][1] = Ac[(rm + 8) * EXP_STRIDE + kc];
                a[mt][2] = Ac[rm * EXP_STRIDE + kc + 4];
                a[mt][3] = Ac[(rm + 8) * EXP_STRIDE + kc + 4];
            }
            #pragma unroll
            for (int nt = 0; nt < 8; nt++) {
                int rn = wn * 64 + nt * 8 + g;
                b[nt][0] = Bc[rn * EXP_STRIDE + kc];
                b[nt][1] = Bc[rn * EXP_STRIDE + kc + 4];
            }
            #pragma unroll
            for (int mt = 0; mt < 2; mt++)
                #pragma unroll
                for (int nt = 0; nt < 8; nt++)
                    mma_tf32(acc[mt][nt], a[mt], b[nt]);
        }
    }

    #pragma unroll
    for (int mt = 0; mt < 2; mt++)
        #pragma unroll
        for (int half = 0; half < 2; half++) {
            int r = wm * 32 + mt * 16 + g + half * 8;
            if (base + r < cnt) {
                int ent = s_ent[r];
                int tok = ent >> 2, slot = ent & 3;
                float p = s_prob[r];
                float* op = out + (size_t)tok * OUTW + slot * HDIM;
                #pragma unroll
                for (int nt = 0; nt < 8; nt++) {
                    int col = wn * 64 + nt * 8 + 2 * t;
                    float2 v;
                    v.x = (acc[mt][nt][half * 2 + 0] + s_bias[col]) * p;
                    v.y = (acc[mt][nt][half * 2 + 1] + s_bias[col + 1]) * p;
                    *(float2*)&op[col] = v;
                }
            }
        }
}

// ============================================================
extern "C" void kernel_launch(void* const* d_in, const int* in_sizes, int n_in,
                              void* d_out, int out_size) {
    const float* x    = (const float*)d_in[0];  // [4,4096,2048]
    const float* rw   = (const float*)d_in[1];  // [256,2048]
    const float* cent = (const float*)d_in[2];  // [16,256]
    const float* temp = (const float*)d_in[3];  // [1]
    const float* w    = (const float*)d_in[4];  // [2048,2048]
    const float* b    = (const float*)d_in[5];  // [2048]
    float* out = (float*)d_out;                 // [4,4096,512]

    cudaFuncSetAttribute(gemm_expert_cp,
                         cudaFuncAttributeMaxDynamicSharedMemorySize,
                         EXP_DYN_BYTES);

    prep_kernel<<<1, 256>>>(cent);
    dprep_kernel<<<16, 256>>>(rw);
    wprep_kernel<<<(NHEAD * HDIM * DIN / 4) / 256, 256>>>(w);
    zn_kernel<<<dim3(2, 128), 256>>>(x, rw);
    lroute_fast<<<1024, 256>>>(x, temp);
    fallback_kernel<<<128, 256>>>(x, rw, temp);
    gemm_expert_cp<<<dim3(128, 16), 256, EXP_DYN_BYTES>>>(b, out);
}

// round 13
// speedup vs baseline: 1.0991x; 1.0991x over previous
#include <cuda_runtime.h>
#include <cuda_bf16.h>
#include <math.h>

#define TOK   16384      // B*S = 4*4096
#define DIN   2048
#define HIDN  256
#define NHEAD 16
#define HDIM  128
#define KSEL  4
#define OUTW  (KSEL*HDIM)   // 512

// ---- device scratch (no allocations allowed) ----
__device__ float g_prob[TOK * KSEL];     // gate prob per (token, slot)
__device__ int   g_list[NHEAD * TOK];    // per-head token*4+slot lists
__device__ int   g_cnt[NHEAD];           // per-head counts
__device__ float g_cnorm[NHEAD * HIDN];  // normalized centroids
__device__ float g_d[NHEAD * DIN];       // d_n = Wr^T c_norm_n  [16][2048]
__device__ float g_n2p[4][TOK];          // ||z||^2 partials (deterministic)
__device__ int   g_flag[TOK];            // flagged (ambiguous) tokens
__device__ int   g_nflag;                // count

// ---- mma helpers ----
__device__ __forceinline__ unsigned f2tf32(float x) {
    unsigned r;
    asm("cvt.rna.tf32.f32 %0, %1;" : "=r"(r) : "f"(x));
    return r;
}
__device__ __forceinline__ void mma_tf32(float* c, const unsigned* a, const unsigned* b) {
    asm volatile(
        "mma.sync.aligned.m16n8k8.row.col.f32.tf32.tf32.f32 "
        "{%0,%1,%2,%3}, {%4,%5,%6,%7}, {%8,%9}, {%0,%1,%2,%3};"
        : "+f"(c[0]), "+f"(c[1]), "+f"(c[2]), "+f"(c[3])
        : "r"(a[0]), "r"(a[1]), "r"(a[2]), "r"(a[3]), "r"(b[0]), "r"(b[1]));
}
__device__ __forceinline__ void mma_bf16(float* c, const unsigned* a, const unsigned* b) {
    asm volatile(
        "mma.sync.aligned.m16n8k16.row.col.f32.bf16.bf16.f32 "
        "{%0,%1,%2,%3}, {%4,%5,%6,%7}, {%8,%9}, {%0,%1,%2,%3};"
        : "+f"(c[0]), "+f"(c[1]), "+f"(c[2]), "+f"(c[3])
        : "r"(a[0]), "r"(a[1]), "r"(a[2]), "r"(a[3]), "r"(b[0]), "r"(b[1]));
}
__device__ __forceinline__ unsigned pack_bf16(float x, float y) {
    __nv_bfloat162 p = __floats2bfloat162_rn(x, y);
    return *reinterpret_cast<unsigned*>(&p);
}

// ============================================================
// Kernel 0: zero counters + normalize centroids
// ============================================================
__global__ void prep_kernel(const float* __restrict__ cent) {
    int tid = threadIdx.x;
    if (tid < NHEAD) g_cnt[tid] = 0;
    if (tid == 0) g_nflag = 0;
    int w = tid >> 5, lane = tid & 31;
    for (int n = w; n < NHEAD; n += 8) {
        float s = 0.f;
        for (int i = lane; i < HIDN; i += 32) {
            float v = cent[n * HIDN + i];
            s += v * v;
        }
        #pragma unroll
        for (int o = 16; o; o >>= 1) s += __shfl_xor_sync(0xffffffffu, s, o);
        float inv = 1.0f / fmaxf(sqrtf(s), 1e-12f);
        for (int i = lane; i < HIDN; i += 32)
            g_cnorm[n * HIDN + i] = cent[n * HIDN + i] * inv;
    }
}

// ============================================================
// Kernel 1: d[n][k] = sum_h c_norm[n][h] * Wr[h][k]   (fp32 exact)
// ============================================================
__global__ void dprep_kernel(const float* __restrict__ Wr) {
    __shared__ float cn[16][256];
    __shared__ float Ws[32][128];
    int tid = threadIdx.x;
    int kbase = blockIdx.x * 128;
    for (int i = tid; i < 16 * 256; i += 256) cn[i >> 8][i & 255] = g_cnorm[i];
    int kk = tid & 127, grp = tid >> 7;
    float acc[8] = {0.f, 0.f, 0.f, 0.f, 0.f, 0.f, 0.f, 0.f};
    for (int hc = 0; hc < 256; hc += 32) {
        __syncthreads();
        for (int i = tid; i < 32 * 128; i += 256) {
            int r = i >> 7, c = i & 127;
            Ws[r][c] = Wr[(size_t)(hc + r) * DIN + kbase + c];
        }
        __syncthreads();
        #pragma unroll 8
        for (int hh = 0; hh < 32; hh++) {
            float wv = Ws[hh][kk];
            #pragma unroll
            for (int i = 0; i < 8; i++)
                acc[i] += cn[grp * 8 + i][hc + hh] * wv;
        }
    }
    #pragma unroll
    for (int i = 0; i < 8; i++)
        g_d[(grp * 8 + i) * DIN + kbase + kk] = acc[i];
}

// ============================================================
// Kernel 2: ||z||^2 via bf16 mma (2-stage pipelined). Values only.
// (VERBATIM R8/R10 — proven)
// ============================================================
__global__ __launch_bounds__(256, 2) void zn_kernel(
    const float* __restrict__ X, const float* __restrict__ Wr) {
    __shared__ unsigned As[2][128][12];
    __shared__ unsigned Bs[2][128][12];

    int tid = threadIdx.x;
    int m0 = blockIdx.y * 128;
    int n0 = blockIdx.x * 128;
    int wid = tid >> 5, lane = tid & 31;
    int wm = wid >> 1, wn = wid & 1;
    int g = lane >> 2, t = lane & 3;

    const float* aptr[2];
    const float* bptr[2];
    int rowL[2], c4L[2];
    #pragma unroll
    for (int i = 0; i < 2; i++) {
        int idx = tid + i * 256;
        rowL[i] = idx >> 2;
        c4L[i] = idx & 3;
        aptr[i] = X  + (size_t)(m0 + rowL[i]) * DIN + c4L[i] * 4;
        bptr[i] = Wr + (size_t)(n0 + rowL[i]) * DIN + c4L[i] * 4;
    }

    float acc[2][8][4];
    #pragma unroll
    for (int i = 0; i < 2; i++)
        #pragma unroll
        for (int j = 0; j < 8; j++)
            #pragma unroll
            for (int q = 0; q < 4; q++) acc[i][j][q] = 0.f;

    float4 av[2], bv[2];
    #pragma unroll
    for (int i = 0; i < 2; i++) {
        av[i] = *(const float4*)aptr[i];
        bv[i] = *(const float4*)bptr[i];
    }
    #pragma unroll
    for (int i = 0; i < 2; i++) {
        As[0][rowL[i]][c4L[i] * 2 + 0] = pack_bf16(av[i].x, av[i].y);
        As[0][rowL[i]][c4L[i] * 2 + 1] = pack_bf16(av[i].z, av[i].w);
        Bs[0][rowL[i]][c4L[i] * 2 + 0] = pack_bf16(bv[i].x, bv[i].y);
        Bs[0][rowL[i]][c4L[i] * 2 + 1] = pack_bf16(bv[i].z, bv[i].w);
    }
    __syncthreads();

    int cur = 0;
    for (int k0 = 0; k0 < DIN; k0 += 16) {
        bool nxt = (k0 + 16) < DIN;
        if (nxt) {
            #pragma unroll
            for (int i = 0; i < 2; i++) {
                av[i] = *(const float4*)(aptr[i] + k0 + 16);
                bv[i] = *(const float4*)(bptr[i] + k0 + 16);
            }
        }
        {
            unsigned a[2][4], b[8][2];
            #pragma unroll
            for (int mt = 0; mt < 2; mt++) {
                int rm = wm * 32 + mt * 16 + g;
                a[mt][0] = As[cur][rm][t];
                a[mt][1] = As[cur][rm + 8][t];
                a[mt][2] = As[cur][rm][t + 4];
                a[mt][3] = As[cur][rm + 8][t + 4];
            }
            #pragma unroll
            for (int nt = 0; nt < 8; nt++) {
                int rn = wn * 64 + nt * 8 + g;
                b[nt][0] = Bs[cur][rn][t];
                b[nt][1] = Bs[cur][rn][t + 4];
            }
            #pragma unroll
            for (int mt = 0; mt < 2; mt++)
                #pragma unroll
                for (int nt = 0; nt < 8; nt++)
                    mma_bf16(acc[mt][nt], a[mt], b[nt]);
        }
        if (nxt) {
            int st = cur ^ 1;
            #pragma unroll
            for (int i = 0; i < 2; i++) {
                As[st][rowL[i]][c4L[i] * 2 + 0] = pack_bf16(av[i].x, av[i].y);
                As[st][rowL[i]][c4L[i] * 2 + 1] = pack_bf16(av[i].z, av[i].w);
                Bs[st][rowL[i]][c4L[i] * 2 + 0] = pack_bf16(bv[i].x, bv[i].y);
                Bs[st][rowL[i]][c4L[i] * 2 + 1] = pack_bf16(bv[i].z, bv[i].w);
            }
        }
        __syncthreads();
        cur ^= 1;
    }

    int p = blockIdx.x * 2 + wn;
    #pragma unroll
    for (int mt = 0; mt < 2; mt++) {
        float s0 = 0.f, s1 = 0.f;
        #pragma unroll
        for (int nt = 0; nt < 8; nt++) {
            s0 += acc[mt][nt][0] * acc[mt][nt][0] + acc[mt][nt][1] * acc[mt][nt][1];
            s1 += acc[mt][nt][2] * acc[mt][nt][2] + acc[mt][nt][3] * acc[mt][nt][3];
        }
        s0 += __shfl_xor_sync(0xffffffffu, s0, 1);
        s0 += __shfl_xor_sync(0xffffffffu, s0, 2);
        s1 += __shfl_xor_sync(0xffffffffu, s1, 1);
        s1 += __shfl_xor_sync(0xffffffffu, s1, 2);
        if (t == 0) {
            int r = m0 + wm * 32 + mt * 16 + g;
            g_n2p[p][r] = s0;
            g_n2p[p][r + 8] = s1;
        }
    }
}

// ============================================================
// Kernel 3: fast routing, 2 tokens per warp (VERBATIM R10 winner)
// ============================================================
__global__ __launch_bounds__(256) void lroute_fast(
    const float* __restrict__ X, const float* __restrict__ temp) {
    __shared__ float ds[16][512];
    int tid = threadIdx.x, lane = tid & 31, w = tid >> 5;
    int tbase = blockIdx.x * 16 + w * 2;
    const float* xr0 = X + (size_t)tbase * DIN;

    float acc[2][16];
    #pragma unroll
    for (int q = 0; q < 2; q++)
        #pragma unroll
        for (int n = 0; n < 16; n++) acc[q][n] = 0.f;

    for (int c = 0; c < 4; c++) {
        __syncthreads();
        for (int i = tid; i < 16 * 128; i += 256) {
            int n = i >> 7, j = i & 127;
            *(float4*)&ds[n][j * 4] = *(const float4*)&g_d[n * DIN + c * 512 + j * 4];
        }
        __syncthreads();
        #pragma unroll
        for (int it = 0; it < 4; it++) {
            int k4 = it * 32 + lane;
            float4 xv0 = *(const float4*)&xr0[c * 512 + k4 * 4];
            float4 xv1 = *(const float4*)&xr0[DIN + c * 512 + k4 * 4];
            #pragma unroll
            for (int n = 0; n < 16; n++) {
                float4 dv = *(const float4*)&ds[n][k4 * 4];
                acc[0][n] += xv0.x * dv.x + xv0.y * dv.y + xv0.z * dv.z + xv0.w * dv.w;
                acc[1][n] += xv1.x * dv.x + xv1.y * dv.y + xv1.z * dv.z + xv1.w * dv.w;
            }
        }
    }
    #pragma unroll
    for (int o = 16; o; o >>= 1)
        #pragma unroll
        for (int q = 0; q < 2; q++)
            #pragma unroll
            for (int n = 0; n < 16; n++)
                acc[q][n] += __shfl_xor_sync(0xffffffffu, acc[q][n], o);

    if (lane < 2) {
        int q = lane;
        int t = tbase + q;
        float u[16];
        #pragma unroll
        for (int n = 0; n < 16; n++) u[n] = acc[q][n];
        float S = 0.f;
        #pragma unroll
        for (int n = 0; n < 16; n++) S = fmaxf(S, fabsf(u[n]));
        float v5[5];
        int i5[5];
        bool used[16];
        #pragma unroll
        for (int n = 0; n < 16; n++) used[n] = false;
        #pragma unroll
        for (int r = 0; r < 5; r++) {
            int bi = 0;
            float bv = -1e30f;
            #pragma unroll
            for (int n = 0; n < 16; n++)
                if (!used[n] && u[n] > bv) { bv = u[n]; bi = n; }
            used[bi] = true;
            v5[r] = bv;
            i5[r] = bi;
        }
        float tau = 1e-4f * S + 1e-12f;
        bool safe = (v5[0] - v5[1] > tau) && (v5[1] - v5[2] > tau) &&
                    (v5[2] - v5[3] > tau) && (v5[3] - v5[4] > tau);
        if (!safe) {
            int p = atomicAdd(&g_nflag, 1);
            g_flag[p] = t;
        } else {
            float n2 = g_n2p[0][t] + g_n2p[1][t] + g_n2p[2][t] + g_n2p[3][t];
            float inv = 1.0f / fmaxf(sqrtf(n2), 1e-12f);
            float sc = inv * 0.0625f * expf(temp[0]);
            float lg[16];
            float mx = -1e30f;
            #pragma unroll
            for (int n = 0; n < 16; n++) {
                lg[n] = u[n] * sc;
                mx = fmaxf(mx, lg[n]);
            }
            float sum = 0.f;
            #pragma unroll
            for (int n = 0; n < 16; n++) {
                lg[n] = expf(lg[n] - mx);
                sum += lg[n];
            }
            float isum = 1.0f / sum;
            #pragma unroll
            for (int k = 0; k < KSEL; k++) {
                int bi = i5[k];
                g_prob[t * KSEL + k] = lg[bi] * isum;
                int pos = atomicAdd(&g_cnt[bi], 1);
                g_list[bi * TOK + pos] = (t << 2) | k;
            }
        }
    }
}

// ============================================================
// Kernel 4: exact fallback for flagged tokens (bit-identical R1 chain).
// ============================================================
__global__ __launch_bounds__(256) void fallback_kernel(
    const float* __restrict__ X, const float* __restrict__ Wr,
    const float* __restrict__ temp) {
    __shared__ float xs[DIN];
    __shared__ float Wt[256][36];
    __shared__ float zs[256];
    __shared__ float red[8];
    __shared__ float slog[16];

    int nf = g_nflag;
    int tid = threadIdx.x, lane = tid & 31, w = tid >> 5;

    for (int fi = blockIdx.x; fi < nf; fi += gridDim.x) {
        int t = g_flag[fi];
        for (int i = tid; i < DIN / 4; i += 256)
            *(float4*)&xs[i * 4] = *(const float4*)&X[(size_t)t * DIN + i * 4];
        __syncthreads();
        float acc = 0.f;
        for (int k0 = 0; k0 < DIN; k0 += 32) {
            __syncthreads();
            for (int i = tid; i < 256 * 8; i += 256) {
                int r = i >> 3, c4 = i & 7;
                *(float4*)&Wt[r][c4 * 4] =
                    *(const float4*)&Wr[(size_t)r * DIN + k0 + c4 * 4];
            }
            __syncthreads();
            #pragma unroll
            for (int kk = 0; kk < 32; kk++)
                acc = __fmaf_rn(xs[k0 + kk], Wt[tid][kk], acc);
        }
        __syncthreads();
        float z = acc;
        zs[tid] = z;
        float s = z * z;
        #pragma unroll
        for (int o = 16; o; o >>= 1) s += __shfl_xor_sync(0xffffffffu, s, o);
        if (lane == 0) red[w] = s;
        __syncthreads();
        float tot = 0.f;
        #pragma unroll
        for (int i = 0; i < 8; i++) tot += red[i];
        float inv = 1.0f / fmaxf(sqrtf(tot), 1e-12f);

        for (int n = w; n < NHEAD; n += 8) {
            float p = 0.f;
            for (int i = lane; i < HIDN; i += 32) p += zs[i] * g_cnorm[n * HIDN + i];
            #pragma unroll
            for (int o = 16; o; o >>= 1) p += __shfl_xor_sync(0xffffffffu, p, o);
            if (lane == 0) slog[n] = p;
        }
        __syncthreads();

        if (tid == 0) {
            float sc = inv * 0.0625f * expf(temp[0]);
            float lg[16];
            float mx = -1e30f;
            #pragma unroll
            for (int n = 0; n < NHEAD; n++) {
                lg[n] = slog[n] * sc;
                mx = fmaxf(mx, lg[n]);
            }
            float sum = 0.f;
            #pragma unroll
            for (int n = 0; n < NHEAD; n++) {
                lg[n] = expf(lg[n] - mx);
                sum += lg[n];
            }
            float isum = 1.0f / sum;
            bool used[16];
            #pragma unroll
            for (int n = 0; n < NHEAD; n++) used[n] = false;
            for (int k = 0; k < KSEL; k++) {
                int bi = 0;
                float bv = -1e30f;
                #pragma unroll
                for (int n = 0; n < NHEAD; n++) {
                    if (!used[n] && lg[n] > bv) { bv = lg[n]; bi = n; }
                }
                used[bi] = true;
                g_prob[t * KSEL + k] = bv * isum;
                int pos = atomicAdd(&g_cnt[bi], 1);
                g_list[bi * TOK + pos] = (t << 2) | k;
            }
        }
        __syncthreads();
    }
}

// ============================================================
// Kernel 5: PERSISTENT grouped expert GEMM, tf32 mma, 2-stage
// register-prefetch pipeline (R10 body, bit-identical math).
// 296 CTAs stride over the ~512 real tiles -> no dead blocks,
// balanced waves.
// ============================================================
__global__ __launch_bounds__(256, 2) void gemm_expert_mma(
    const float* __restrict__ X, const float* __restrict__ W,
    const float* __restrict__ bias, float* __restrict__ out) {
    __shared__ unsigned As[2][128][20];
    __shared__ unsigned Bs[2][128][20];
    __shared__ int   s_ent[128];
    __shared__ float s_prob[128];
    __shared__ float s_bias[128];

    int tid = threadIdx.x;
    int wid = tid >> 5, lane = tid & 31;
    int wm = wid >> 1, wn = wid & 1;
    int g = lane >> 2, t = lane & 3;

    // tile map: per head, ceil(cnt/128) tiles
    int ntile[NHEAD], pre[NHEAD + 1];
    pre[0] = 0;
    #pragma unroll
    for (int hh = 0; hh < NHEAD; hh++) {
        ntile[hh] = (g_cnt[hh] + 127) >> 7;
        pre[hh + 1] = pre[hh] + ntile[hh];
    }
    int total = pre[NHEAD];

    for (int tile = blockIdx.x; tile < total; tile += gridDim.x) {
        int h = 0;
        #pragma unroll
        for (int hh = 0; hh < NHEAD; hh++)
            if (tile >= pre[hh + 1]) h = hh + 1;
        int cnt = g_cnt[h];
        int base = (tile - pre[h]) * 128;

        if (tid < 128) {
            int r = base + tid;
            int rr = (r < cnt) ? r : (cnt - 1);
            int ent = g_list[h * TOK + rr];
            s_ent[tid] = ent;
            s_prob[tid] = g_prob[ent];
            s_bias[tid] = bias[h * HDIM + tid];
        }
        __syncthreads();

        const float* Wh = W + (size_t)h * HDIM * DIN;
        const float* aptr[2];
        const float* bptr[2];
        int rowL[2], c4L[2];
        #pragma unroll
        for (int i = 0; i < 2; i++) {
            int idx = tid + i * 256;
            rowL[i] = idx >> 2;
            c4L[i] = idx & 3;
            int tok = s_ent[rowL[i]] >> 2;
            aptr[i] = X  + (size_t)tok * DIN + c4L[i] * 4;
            bptr[i] = Wh + (size_t)rowL[i] * DIN + c4L[i] * 4;
        }

        float acc[2][8][4];
        #pragma unroll
        for (int i = 0; i < 2; i++)
            #pragma unroll
            for (int j = 0; j < 8; j++)
                #pragma unroll
                for (int q = 0; q < 4; q++) acc[i][j][q] = 0.f;

        float4 av[2], bv[2];
        #pragma unroll
        for (int i = 0; i < 2; i++) {
            av[i] = *(const float4*)aptr[i];
            bv[i] = *(const float4*)bptr[i];
        }
        #pragma unroll
        for (int i = 0; i < 2; i++) {
            uint4 u;
            u.x = f2tf32(av[i].x); u.y = f2tf32(av[i].y);
            u.z = f2tf32(av[i].z); u.w = f2tf32(av[i].w);
            *(uint4*)&As[0][rowL[i]][c4L[i] * 4] = u;
            u.x = f2tf32(bv[i].x); u.y = f2tf32(bv[i].y);
            u.z = f2tf32(bv[i].z); u.w = f2tf32(bv[i].w);
            *(uint4*)&Bs[0][rowL[i]][c4L[i] * 4] = u;
        }
        __syncthreads();

        int cur = 0;
        for (int k0 = 0; k0 < DIN; k0 += 16) {
            bool nxt = (k0 + 16) < DIN;
            if (nxt) {
                #pragma unroll
                for (int i = 0; i < 2; i++) {
                    av[i] = *(const float4*)(aptr[i] + k0 + 16);
                    bv[i] = *(const float4*)(bptr[i] + k0 + 16);
                }
            }
            #pragma unroll
            for (int s = 0; s < 2; s++) {
                unsigned a[2][4], b[8][2];
                #pragma unroll
                for (int mt = 0; mt < 2; mt++) {
                    int rm = wm * 32 + mt * 16 + g;
                    int kc = s * 8 + t;
                    a[mt][0] = As[cur][rm][kc];
                    a[mt][1] = As[cur][rm + 8][kc];
                    a[mt][2] = As[cur][rm][kc + 4];
                    a[mt][3] = As[cur][rm + 8][kc + 4];
                }
                #pragma unroll
                for (int nt = 0; nt < 8; nt++) {
                    int rn = wn * 64 + nt * 8 + g;
                    int kc = s * 8 + t;
                    b[nt][0] = Bs[cur][rn][kc];
                    b[nt][1] = Bs[cur][rn][kc + 4];
                }
                #pragma unroll
                for (int mt = 0; mt < 2; mt++)
                    #pragma unroll
                    for (int nt = 0; nt < 8; nt++)
                        mma_tf32(acc[mt][nt], a[mt], b[nt]);
            }
            if (nxt) {
                int st = cur ^ 1;
                #pragma unroll
                for (int i = 0; i < 2; i++) {
                    uint4 u;
                    u.x = f2tf32(av[i].x); u.y = f2tf32(av[i].y);
                    u.z = f2tf32(av[i].z); u.w = f2tf32(av[i].w);
                    *(uint4*)&As[st][rowL[i]][c4L[i] * 4] = u;
                    u.x = f2tf32(bv[i].x); u.y = f2tf32(bv[i].y);
                    u.z = f2tf32(bv[i].z); u.w = f2tf32(bv[i].w);
                    *(uint4*)&Bs[st][rowL[i]][c4L[i] * 4] = u;
                }
            }
            __syncthreads();
            cur ^= 1;
        }

        #pragma unroll
        for (int mt = 0; mt < 2; mt++)
            #pragma unroll
            for (int half = 0; half < 2; half++) {
                int r = wm * 32 + mt * 16 + g + half * 8;
                if (base + r < cnt) {
                    int ent = s_ent[r];
                    int tok = ent >> 2, slot = ent & 3;
                    float p = s_prob[r];
                    float* op = out + (size_t)tok * OUTW + slot * HDIM;
                    #pragma unroll
                    for (int nt = 0; nt < 8; nt++) {
                        int col = wn * 64 + nt * 8 + 2 * t;
                        float2 v;
                        v.x = (acc[mt][nt][half * 2 + 0] + s_bias[col]) * p;
                        v.y = (acc[mt][nt][half * 2 + 1] + s_bias[col + 1]) * p;
                        *(float2*)&op[col] = v;
                    }
                }
            }
        __syncthreads();   // protect s_ent/s_prob/s_bias before next tile
    }
}

// ============================================================
extern "C" void kernel_launch(void* const* d_in, const int* in_sizes, int n_in,
                              void* d_out, int out_size) {
    const float* x    = (const float*)d_in[0];  // [4,4096,2048]
    const float* rw   = (const float*)d_in[1];  // [256,2048]
    const float* cent = (const float*)d_in[2];  // [16,256]
    const float* temp = (const float*)d_in[3];  // [1]
    const float* w    = (const float*)d_in[4];  // [2048,2048]
    const float* b    = (const float*)d_in[5];  // [2048]
    float* out = (float*)d_out;                 // [4,4096,512]

    prep_kernel<<<1, 256>>>(cent);
    dprep_kernel<<<16, 256>>>(rw);
    zn_kernel<<<dim3(2, 128), 256>>>(x, rw);
    lroute_fast<<<1024, 256>>>(x, temp);
    fallback_kernel<<<128, 256>>>(x, rw, temp);
    gemm_expert_mma<<<296, 256>>>(x, w, b, out);
}

// round 14
// speedup vs baseline: 1.2140x; 1.1046x over previous
#include <cuda_runtime.h>
#include <cuda_bf16.h>
#include <math.h>

#define TOK   16384      // B*S = 4*4096
#define DIN   2048
#define HIDN  256
#define NHEAD 16
#define HDIM  128
#define KSEL  4
#define OUTW  (KSEL*HDIM)   // 512

// ---- device scratch (no allocations allowed) ----
__device__ float g_prob[TOK * KSEL];     // gate prob per (token, slot)
__device__ int   g_list[NHEAD * TOK];    // per-head token*4+slot lists
__device__ int   g_cnt[NHEAD];           // per-head counts
__device__ float g_cnorm[NHEAD * HIDN];  // normalized centroids
__device__ float g_d[NHEAD * DIN];       // d_n = Wr^T c_norm_n  [16][2048]
__device__ float g_n2p[4][TOK];          // ||z||^2 partials (deterministic)
__device__ int   g_flag[TOK];            // flagged (ambiguous) tokens
__device__ int   g_nflag;                // count

// ---- mma helpers ----
__device__ __forceinline__ unsigned f2tf32(float x) {
    unsigned r;
    asm("cvt.rna.tf32.f32 %0, %1;" : "=r"(r) : "f"(x));
    return r;
}
__device__ __forceinline__ void mma_tf32(float* c, const unsigned* a, const unsigned* b) {
    asm volatile(
        "mma.sync.aligned.m16n8k8.row.col.f32.tf32.tf32.f32 "
        "{%0,%1,%2,%3}, {%4,%5,%6,%7}, {%8,%9}, {%0,%1,%2,%3};"
        : "+f"(c[0]), "+f"(c[1]), "+f"(c[2]), "+f"(c[3])
        : "r"(a[0]), "r"(a[1]), "r"(a[2]), "r"(a[3]), "r"(b[0]), "r"(b[1]));
}
__device__ __forceinline__ void mma_bf16(float* c, const unsigned* a, const unsigned* b) {
    asm volatile(
        "mma.sync.aligned.m16n8k16.row.col.f32.bf16.bf16.f32 "
        "{%0,%1,%2,%3}, {%4,%5,%6,%7}, {%8,%9}, {%0,%1,%2,%3};"
        : "+f"(c[0]), "+f"(c[1]), "+f"(c[2]), "+f"(c[3])
        : "r"(a[0]), "r"(a[1]), "r"(a[2]), "r"(a[3]), "r"(b[0]), "r"(b[1]));
}
__device__ __forceinline__ unsigned pack_bf16(float x, float y) {
    __nv_bfloat162 p = __floats2bfloat162_rn(x, y);
    return *reinterpret_cast<unsigned*>(&p);
}

// ============================================================
// Kernel 0: zero counters + normalize centroids
// ============================================================
__global__ void prep_kernel(const float* __restrict__ cent) {
    int tid = threadIdx.x;
    if (tid < NHEAD) g_cnt[tid] = 0;
    if (tid == 0) g_nflag = 0;
    int w = tid >> 5, lane = tid & 31;
    for (int n = w; n < NHEAD; n += 8) {
        float s = 0.f;
        for (int i = lane; i < HIDN; i += 32) {
            float v = cent[n * HIDN + i];
            s += v * v;
        }
        #pragma unroll
        for (int o = 16; o; o >>= 1) s += __shfl_xor_sync(0xffffffffu, s, o);
        float inv = 1.0f / fmaxf(sqrtf(s), 1e-12f);
        for (int i = lane; i < HIDN; i += 32)
            g_cnorm[n * HIDN + i] = cent[n * HIDN + i] * inv;
    }
}

// ============================================================
// Kernel 1: d[n][k] = sum_h c_norm[n][h] * Wr[h][k]   (fp32 exact)
// ============================================================
__global__ void dprep_kernel(const float* __restrict__ Wr) {
    __shared__ float cn[16][256];
    __shared__ float Ws[32][128];
    int tid = threadIdx.x;
    int kbase = blockIdx.x * 128;
    for (int i = tid; i < 16 * 256; i += 256) cn[i >> 8][i & 255] = g_cnorm[i];
    int kk = tid & 127, grp = tid >> 7;
    float acc[8] = {0.f, 0.f, 0.f, 0.f, 0.f, 0.f, 0.f, 0.f};
    for (int hc = 0; hc < 256; hc += 32) {
        __syncthreads();
        for (int i = tid; i < 32 * 128; i += 256) {
            int r = i >> 7, c = i & 127;
            Ws[r][c] = Wr[(size_t)(hc + r) * DIN + kbase + c];
        }
        __syncthreads();
        #pragma unroll 8
        for (int hh = 0; hh < 32; hh++) {
            float wv = Ws[hh][kk];
            #pragma unroll
            for (int i = 0; i < 8; i++)
                acc[i] += cn[grp * 8 + i][hc + hh] * wv;
        }
    }
    #pragma unroll
    for (int i = 0; i < 8; i++)
        g_d[(grp * 8 + i) * DIN + kbase + kk] = acc[i];
}

// ============================================================
// Kernel 2: ||z||^2 via bf16 mma (2-stage pipelined). Values only.
// (VERBATIM R8/R10 — proven)
// ============================================================
__global__ __launch_bounds__(256, 2) void zn_kernel(
    const float* __restrict__ X, const float* __restrict__ Wr) {
    __shared__ unsigned As[2][128][12];
    __shared__ unsigned Bs[2][128][12];

    int tid = threadIdx.x;
    int m0 = blockIdx.y * 128;
    int n0 = blockIdx.x * 128;
    int wid = tid >> 5, lane = tid & 31;
    int wm = wid >> 1, wn = wid & 1;
    int g = lane >> 2, t = lane & 3;

    const float* aptr[2];
    const float* bptr[2];
    int rowL[2], c4L[2];
    #pragma unroll
    for (int i = 0; i < 2; i++) {
        int idx = tid + i * 256;
        rowL[i] = idx >> 2;
        c4L[i] = idx & 3;
        aptr[i] = X  + (size_t)(m0 + rowL[i]) * DIN + c4L[i] * 4;
        bptr[i] = Wr + (size_t)(n0 + rowL[i]) * DIN + c4L[i] * 4;
    }

    float acc[2][8][4];
    #pragma unroll
    for (int i = 0; i < 2; i++)
        #pragma unroll
        for (int j = 0; j < 8; j++)
            #pragma unroll
            for (int q = 0; q < 4; q++) acc[i][j][q] = 0.f;

    float4 av[2], bv[2];
    #pragma unroll
    for (int i = 0; i < 2; i++) {
        av[i] = *(const float4*)aptr[i];
        bv[i] = *(const float4*)bptr[i];
    }
    #pragma unroll
    for (int i = 0; i < 2; i++) {
        As[0][rowL[i]][c4L[i] * 2 + 0] = pack_bf16(av[i].x, av[i].y);
        As[0][rowL[i]][c4L[i] * 2 + 1] = pack_bf16(av[i].z, av[i].w);
        Bs[0][rowL[i]][c4L[i] * 2 + 0] = pack_bf16(bv[i].x, bv[i].y);
        Bs[0][rowL[i]][c4L[i] * 2 + 1] = pack_bf16(bv[i].z, bv[i].w);
    }
    __syncthreads();

    int cur = 0;
    for (int k0 = 0; k0 < DIN; k0 += 16) {
        bool nxt = (k0 + 16) < DIN;
        if (nxt) {
            #pragma unroll
            for (int i = 0; i < 2; i++) {
                av[i] = *(const float4*)(aptr[i] + k0 + 16);
                bv[i] = *(const float4*)(bptr[i] + k0 + 16);
            }
        }
        {
            unsigned a[2][4], b[8][2];
            #pragma unroll
            for (int mt = 0; mt < 2; mt++) {
                int rm = wm * 32 + mt * 16 + g;
                a[mt][0] = As[cur][rm][t];
                a[mt][1] = As[cur][rm + 8][t];
                a[mt][2] = As[cur][rm][t + 4];
                a[mt][3] = As[cur][rm + 8][t + 4];
            }
            #pragma unroll
            for (int nt = 0; nt < 8; nt++) {
                int rn = wn * 64 + nt * 8 + g;
                b[nt][0] = Bs[cur][rn][t];
                b[nt][1] = Bs[cur][rn][t + 4];
            }
            #pragma unroll
            for (int mt = 0; mt < 2; mt++)
                #pragma unroll
                for (int nt = 0; nt < 8; nt++)
                    mma_bf16(acc[mt][nt], a[mt], b[nt]);
        }
        if (nxt) {
            int st = cur ^ 1;
            #pragma unroll
            for (int i = 0; i < 2; i++) {
                As[st][rowL[i]][c4L[i] * 2 + 0] = pack_bf16(av[i].x, av[i].y);
                As[st][rowL[i]][c4L[i] * 2 + 1] = pack_bf16(av[i].z, av[i].w);
                Bs[st][rowL[i]][c4L[i] * 2 + 0] = pack_bf16(bv[i].x, bv[i].y);
                Bs[st][rowL[i]][c4L[i] * 2 + 1] = pack_bf16(bv[i].z, bv[i].w);
            }
        }
        __syncthreads();
        cur ^= 1;
    }

    int p = blockIdx.x * 2 + wn;
    #pragma unroll
    for (int mt = 0; mt < 2; mt++) {
        float s0 = 0.f, s1 = 0.f;
        #pragma unroll
        for (int nt = 0; nt < 8; nt++) {
            s0 += acc[mt][nt][0] * acc[mt][nt][0] + acc[mt][nt][1] * acc[mt][nt][1];
            s1 += acc[mt][nt][2] * acc[mt][nt][2] + acc[mt][nt][3] * acc[mt][nt][3];
        }
        s0 += __shfl_xor_sync(0xffffffffu, s0, 1);
        s0 += __shfl_xor_sync(0xffffffffu, s0, 2);
        s1 += __shfl_xor_sync(0xffffffffu, s1, 1);
        s1 += __shfl_xor_sync(0xffffffffu, s1, 2);
        if (t == 0) {
            int r = m0 + wm * 32 + mt * 16 + g;
            g_n2p[p][r] = s0;
            g_n2p[p][r + 8] = s1;
        }
    }
}

// ============================================================
// Kernel 3: fast routing, 2 tokens per warp (VERBATIM R10 winner)
// ============================================================
__global__ __launch_bounds__(256) void lroute_fast(
    const float* __restrict__ X, const float* __restrict__ temp) {
    __shared__ float ds[16][512];
    int tid = threadIdx.x, lane = tid & 31, w = tid >> 5;
    int tbase = blockIdx.x * 16 + w * 2;
    const float* xr0 = X + (size_t)tbase * DIN;

    float acc[2][16];
    #pragma unroll
    for (int q = 0; q < 2; q++)
        #pragma unroll
        for (int n = 0; n < 16; n++) acc[q][n] = 0.f;

    for (int c = 0; c < 4; c++) {
        __syncthreads();
        for (int i = tid; i < 16 * 128; i += 256) {
            int n = i >> 7, j = i & 127;
            *(float4*)&ds[n][j * 4] = *(const float4*)&g_d[n * DIN + c * 512 + j * 4];
        }
        __syncthreads();
        #pragma unroll
        for (int it = 0; it < 4; it++) {
            int k4 = it * 32 + lane;
            float4 xv0 = *(const float4*)&xr0[c * 512 + k4 * 4];
            float4 xv1 = *(const float4*)&xr0[DIN + c * 512 + k4 * 4];
            #pragma unroll
            for (int n = 0; n < 16; n++) {
                float4 dv = *(const float4*)&ds[n][k4 * 4];
                acc[0][n] += xv0.x * dv.x + xv0.y * dv.y + xv0.z * dv.z + xv0.w * dv.w;
                acc[1][n] += xv1.x * dv.x + xv1.y * dv.y + xv1.z * dv.z + xv1.w * dv.w;
            }
        }
    }
    #pragma unroll
    for (int o = 16; o; o >>= 1)
        #pragma unroll
        for (int q = 0; q < 2; q++)
            #pragma unroll
            for (int n = 0; n < 16; n++)
                acc[q][n] += __shfl_xor_sync(0xffffffffu, acc[q][n], o);

    if (lane < 2) {
        int q = lane;
        int t = tbase + q;
        float u[16];
        #pragma unroll
        for (int n = 0; n < 16; n++) u[n] = acc[q][n];
        float S = 0.f;
        #pragma unroll
        for (int n = 0; n < 16; n++) S = fmaxf(S, fabsf(u[n]));
        float v5[5];
        int i5[5];
        bool used[16];
        #pragma unroll
        for (int n = 0; n < 16; n++) used[n] = false;
        #pragma unroll
        for (int r = 0; r < 5; r++) {
            int bi = 0;
            float bv = -1e30f;
            #pragma unroll
            for (int n = 0; n < 16; n++)
                if (!used[n] && u[n] > bv) { bv = u[n]; bi = n; }
            used[bi] = true;
            v5[r] = bv;
            i5[r] = bi;
        }
        float tau = 1e-4f * S + 1e-12f;
        bool safe = (v5[0] - v5[1] > tau) && (v5[1] - v5[2] > tau) &&
                    (v5[2] - v5[3] > tau) && (v5[3] - v5[4] > tau);
        if (!safe) {
            int p = atomicAdd(&g_nflag, 1);
            g_flag[p] = t;
        } else {
            float n2 = g_n2p[0][t] + g_n2p[1][t] + g_n2p[2][t] + g_n2p[3][t];
            float inv = 1.0f / fmaxf(sqrtf(n2), 1e-12f);
            float sc = inv * 0.0625f * expf(temp[0]);
            float lg[16];
            float mx = -1e30f;
            #pragma unroll
            for (int n = 0; n < 16; n++) {
                lg[n] = u[n] * sc;
                mx = fmaxf(mx, lg[n]);
            }
            float sum = 0.f;
            #pragma unroll
            for (int n = 0; n < 16; n++) {
                lg[n] = expf(lg[n] - mx);
                sum += lg[n];
            }
            float isum = 1.0f / sum;
            #pragma unroll
            for (int k = 0; k < KSEL; k++) {
                int bi = i5[k];
                g_prob[t * KSEL + k] = lg[bi] * isum;
                int pos = atomicAdd(&g_cnt[bi], 1);
                g_list[bi * TOK + pos] = (t << 2) | k;
            }
        }
    }
}

// ============================================================
// Kernel 4: exact fallback for flagged tokens (bit-identical R1 chain).
// ============================================================
__global__ __launch_bounds__(256) void fallback_kernel(
    const float* __restrict__ X, const float* __restrict__ Wr,
    const float* __restrict__ temp) {
    __shared__ float xs[DIN];
    __shared__ float Wt[256][36];
    __shared__ float zs[256];
    __shared__ float red[8];
    __shared__ float slog[16];

    int nf = g_nflag;
    int tid = threadIdx.x, lane = tid & 31, w = tid >> 5;

    for (int fi = blockIdx.x; fi < nf; fi += gridDim.x) {
        int t = g_flag[fi];
        for (int i = tid; i < DIN / 4; i += 256)
            *(float4*)&xs[i * 4] = *(const float4*)&X[(size_t)t * DIN + i * 4];
        __syncthreads();
        float acc = 0.f;
        for (int k0 = 0; k0 < DIN; k0 += 32) {
            __syncthreads();
            for (int i = tid; i < 256 * 8; i += 256) {
                int r = i >> 3, c4 = i & 7;
                *(float4*)&Wt[r][c4 * 4] =
                    *(const float4*)&Wr[(size_t)r * DIN + k0 + c4 * 4];
            }
            __syncthreads();
            #pragma unroll
            for (int kk = 0; kk < 32; kk++)
                acc = __fmaf_rn(xs[k0 + kk], Wt[tid][kk], acc);
        }
        __syncthreads();
        float z = acc;
        zs[tid] = z;
        float s = z * z;
        #pragma unroll
        for (int o = 16; o; o >>= 1) s += __shfl_xor_sync(0xffffffffu, s, o);
        if (lane == 0) red[w] = s;
        __syncthreads();
        float tot = 0.f;
        #pragma unroll
        for (int i = 0; i < 8; i++) tot += red[i];
        float inv = 1.0f / fmaxf(sqrtf(tot), 1e-12f);

        for (int n = w; n < NHEAD; n += 8) {
            float p = 0.f;
            for (int i = lane; i < HIDN; i += 32) p += zs[i] * g_cnorm[n * HIDN + i];
            #pragma unroll
            for (int o = 16; o; o >>= 1) p += __shfl_xor_sync(0xffffffffu, p, o);
            if (lane == 0) slog[n] = p;
        }
        __syncthreads();

        if (tid == 0) {
            float sc = inv * 0.0625f * expf(temp[0]);
            float lg[16];
            float mx = -1e30f;
            #pragma unroll
            for (int n = 0; n < NHEAD; n++) {
                lg[n] = slog[n] * sc;
                mx = fmaxf(mx, lg[n]);
            }
            float sum = 0.f;
            #pragma unroll
            for (int n = 0; n < NHEAD; n++) {
                lg[n] = expf(lg[n] - mx);
                sum += lg[n];
            }
            float isum = 1.0f / sum;
            bool used[16];
            #pragma unroll
            for (int n = 0; n < NHEAD; n++) used[n] = false;
            for (int k = 0; k < KSEL; k++) {
                int bi = 0;
                float bv = -1e30f;
                #pragma unroll
                for (int n = 0; n < NHEAD; n++) {
                    if (!used[n] && lg[n] > bv) { bv = lg[n]; bi = n; }
                }
                used[bi] = true;
                g_prob[t * KSEL + k] = bv * isum;
                int pos = atomicAdd(&g_cnt[bi], 1);
                g_list[bi * TOK + pos] = (t << 2) | k;
            }
        }
        __syncthreads();
    }
}

// ============================================================
// Kernel 5: grouped expert GEMM, tf32 mma, 2-stage pipelined.
// 128 threads (4 warps), warp tile 64x64 -> fragment bytes/mma
// 1.5 -> 1.0 regs (LDS-crossbar relief). Same accumulation chains
// per output element (bit-identical).
// ============================================================
__global__ __launch_bounds__(128, 2) void gemm_expert_mma(
    const float* __restrict__ X, const float* __restrict__ W,
    const float* __restrict__ bias, float* __restrict__ out) {
    int h = blockIdx.y;
    int cnt = g_cnt[h];
    int base = blockIdx.x * 128;
    if (base >= cnt) return;

    __shared__ unsigned As[2][128][20];
    __shared__ unsigned Bs[2][128][20];
    __shared__ int   s_ent[128];
    __shared__ float s_prob[128];
    __shared__ float s_bias[128];

    int tid = threadIdx.x;
    {
        int r = base + tid;
        int rr = (r < cnt) ? r : (cnt - 1);
        int ent = g_list[h * TOK + rr];
        s_ent[tid] = ent;
        s_prob[tid] = g_prob[ent];
        s_bias[tid] = bias[h * HDIM + tid];
    }
    __syncthreads();

    const float* Wh = W + (size_t)h * HDIM * DIN;
    const float* aptr[4];
    const float* bptr[4];
    int rowL[4], c4L[4];
    #pragma unroll
    for (int i = 0; i < 4; i++) {
        int idx = tid + i * 128;
        rowL[i] = idx >> 2;
        c4L[i] = idx & 3;
        int tok = s_ent[rowL[i]] >> 2;
        aptr[i] = X  + (size_t)tok * DIN + c4L[i] * 4;
        bptr[i] = Wh + (size_t)rowL[i] * DIN + c4L[i] * 4;
    }

    int wid = tid >> 5, lane = tid & 31;
    int wm = wid >> 1, wn = wid & 1;
    int g = lane >> 2, t = lane & 3;

    float acc[4][8][4];
    #pragma unroll
    for (int i = 0; i < 4; i++)
        #pragma unroll
        for (int j = 0; j < 8; j++)
            #pragma unroll
            for (int q = 0; q < 4; q++) acc[i][j][q] = 0.f;

    float4 av[4], bv[4];
    #pragma unroll
    for (int i = 0; i < 4; i++) {
        av[i] = *(const float4*)aptr[i];
        bv[i] = *(const float4*)bptr[i];
    }
    #pragma unroll
    for (int i = 0; i < 4; i++) {
        uint4 u;
        u.x = f2tf32(av[i].x); u.y = f2tf32(av[i].y);
        u.z = f2tf32(av[i].z); u.w = f2tf32(av[i].w);
        *(uint4*)&As[0][rowL[i]][c4L[i] * 4] = u;
        u.x = f2tf32(bv[i].x); u.y = f2tf32(bv[i].y);
        u.z = f2tf32(bv[i].z); u.w = f2tf32(bv[i].w);
        *(uint4*)&Bs[0][rowL[i]][c4L[i] * 4] = u;
    }
    __syncthreads();

    int cur = 0;
    for (int k0 = 0; k0 < DIN; k0 += 16) {
        bool nxt = (k0 + 16) < DIN;
        if (nxt) {
            #pragma unroll
            for (int i = 0; i < 4; i++) {
                av[i] = *(const float4*)(aptr[i] + k0 + 16);
                bv[i] = *(const float4*)(bptr[i] + k0 + 16);
            }
        }
        #pragma unroll
        for (int s = 0; s < 2; s++) {
            unsigned a[4][4], b[8][2];
            int kc = s * 8 + t;
            #pragma unroll
            for (int mt = 0; mt < 4; mt++) {
                int rm = wm * 64 + mt * 16 + g;
                a[mt][0] = As[cur][rm][kc];
                a[mt][1] = As[cur][rm + 8][kc];
                a[mt][2] = As[cur][rm][kc + 4];
                a[mt][3] = As[cur][rm + 8][kc + 4];
            }
            #pragma unroll
            for (int nt = 0; nt < 8; nt++) {
                int rn = wn * 64 + nt * 8 + g;
                b[nt][0] = Bs[cur][rn][kc];
                b[nt][1] = Bs[cur][rn][kc + 4];
            }
            #pragma unroll
            for (int mt = 0; mt < 4; mt++)
                #pragma unroll
                for (int nt = 0; nt < 8; nt++)
                    mma_tf32(acc[mt][nt], a[mt], b[nt]);
        }
        if (nxt) {
            int st = cur ^ 1;
            #pragma unroll
            for (int i = 0; i < 4; i++) {
                uint4 u;
                u.x = f2tf32(av[i].x); u.y = f2tf32(av[i].y);
                u.z = f2tf32(av[i].z); u.w = f2tf32(av[i].w);
                *(uint4*)&As[st][rowL[i]][c4L[i] * 4] = u;
                u.x = f2tf32(bv[i].x); u.y = f2tf32(bv[i].y);
                u.z = f2tf32(bv[i].z); u.w = f2tf32(bv[i].w);
                *(uint4*)&Bs[st][rowL[i]][c4L[i] * 4] = u;
            }
        }
        __syncthreads();
        cur ^= 1;
    }

    #pragma unroll
    for (int mt = 0; mt < 4; mt++)
        #pragma unroll
        for (int half = 0; half < 2; half++) {
            int r = wm * 64 + mt * 16 + g + half * 8;
            if (base + r < cnt) {
                int ent = s_ent[r];
                int tok = ent >> 2, slot = ent & 3;
                float p = s_prob[r];
                float* op = out + (size_t)tok * OUTW + slot * HDIM;
                #pragma unroll
                for (int nt = 0; nt < 8; nt++) {
                    int col = wn * 64 + nt * 8 + 2 * t;
                    float2 v;
                    v.x = (acc[mt][nt][half * 2 + 0] + s_bias[col]) * p;
                    v.y = (acc[mt][nt][half * 2 + 1] + s_bias[col + 1]) * p;
                    *(float2*)&op[col] = v;
                }
            }
        }
}

// ============================================================
extern "C" void kernel_launch(void* const* d_in, const int* in_sizes, int n_in,
                              void* d_out, int out_size) {
    const float* x    = (const float*)d_in[0];  // [4,4096,2048]
    const float* rw   = (const float*)d_in[1];  // [256,2048]
    const float* cent = (const float*)d_in[2];  // [16,256]
    const float* temp = (const float*)d_in[3];  // [1]
    const float* w    = (const float*)d_in[4];  // [2048,2048]
    const float* b    = (const float*)d_in[5];  // [2048]
    float* out = (float*)d_out;                 // [4,4096,512]

    prep_kernel<<<1, 256>>>(cent);
    dprep_kernel<<<16, 256>>>(rw);
    zn_kernel<<<dim3(2, 128), 256>>>(x, rw);
    lroute_fast<<<1024, 256>>>(x, temp);
    fallback_kernel<<<128, 256>>>(x, rw, temp);
    gemm_expert_mma<<<dim3(128, 16), 128>>>(x, w, b, out);
}

// round 15
// speedup vs baseline: 1.2308x; 1.0138x over previous
#include <cuda_runtime.h>
#include <cuda_bf16.h>
#include <math.h>

#define TOK   16384      // B*S = 4*4096
#define DIN   2048
#define HIDN  256
#define NHEAD 16
#define HDIM  128
#define KSEL  4
#define OUTW  (KSEL*HDIM)   // 512

// ---- device scratch (no allocations allowed) ----
__device__ float g_prob[TOK * KSEL];     // gate prob per (token, slot)
__device__ int   g_list[NHEAD * TOK];    // per-head token*4+slot lists
__device__ int   g_cnt[NHEAD];           // per-head counts
__device__ float g_cnorm[NHEAD * HIDN];  // normalized centroids
__device__ float g_d[NHEAD * DIN];       // d_n = Wr^T c_norm_n  [16][2048]
__device__ float g_n2p[4][TOK];          // ||z||^2 partials (deterministic)
__device__ int   g_flag[TOK];            // flagged (ambiguous) tokens
__device__ int   g_nflag;                // count

// ---- mma helpers ----
__device__ __forceinline__ unsigned f2tf32(float x) {
    unsigned r;
    asm("cvt.rna.tf32.f32 %0, %1;" : "=r"(r) : "f"(x));
    return r;
}
__device__ __forceinline__ void mma_tf32(float* c, const unsigned* a, const unsigned* b) {
    asm volatile(
        "mma.sync.aligned.m16n8k8.row.col.f32.tf32.tf32.f32 "
        "{%0,%1,%2,%3}, {%4,%5,%6,%7}, {%8,%9}, {%0,%1,%2,%3};"
        : "+f"(c[0]), "+f"(c[1]), "+f"(c[2]), "+f"(c[3])
        : "r"(a[0]), "r"(a[1]), "r"(a[2]), "r"(a[3]), "r"(b[0]), "r"(b[1]));
}
__device__ __forceinline__ void mma_bf16(float* c, const unsigned* a, const unsigned* b) {
    asm volatile(
        "mma.sync.aligned.m16n8k16.row.col.f32.bf16.bf16.f32 "
        "{%0,%1,%2,%3}, {%4,%5,%6,%7}, {%8,%9}, {%0,%1,%2,%3};"
        : "+f"(c[0]), "+f"(c[1]), "+f"(c[2]), "+f"(c[3])
        : "r"(a[0]), "r"(a[1]), "r"(a[2]), "r"(a[3]), "r"(b[0]), "r"(b[1]));
}
__device__ __forceinline__ unsigned pack_bf16(float x, float y) {
    __nv_bfloat162 p = __floats2bfloat162_rn(x, y);
    return *reinterpret_cast<unsigned*>(&p);
}

// ============================================================
// Kernel 0: zero counters + normalize centroids
// ============================================================
__global__ void prep_kernel(const float* __restrict__ cent) {
    int tid = threadIdx.x;
    if (tid < NHEAD) g_cnt[tid] = 0;
    if (tid == 0) g_nflag = 0;
    int w = tid >> 5, lane = tid & 31;
    for (int n = w; n < NHEAD; n += 8) {
        float s = 0.f;
        for (int i = lane; i < HIDN; i += 32) {
            float v = cent[n * HIDN + i];
            s += v * v;
        }
        #pragma unroll
        for (int o = 16; o; o >>= 1) s += __shfl_xor_sync(0xffffffffu, s, o);
        float inv = 1.0f / fmaxf(sqrtf(s), 1e-12f);
        for (int i = lane; i < HIDN; i += 32)
            g_cnorm[n * HIDN + i] = cent[n * HIDN + i] * inv;
    }
}

// ============================================================
// Kernel 1: d[n][k] = sum_h c_norm[n][h] * Wr[h][k]   (fp32 exact)
// ============================================================
__global__ void dprep_kernel(const float* __restrict__ Wr) {
    __shared__ float cn[16][256];
    __shared__ float Ws[32][128];
    int tid = threadIdx.x;
    int kbase = blockIdx.x * 128;
    for (int i = tid; i < 16 * 256; i += 256) cn[i >> 8][i & 255] = g_cnorm[i];
    int kk = tid & 127, grp = tid >> 7;
    float acc[8] = {0.f, 0.f, 0.f, 0.f, 0.f, 0.f, 0.f, 0.f};
    for (int hc = 0; hc < 256; hc += 32) {
        __syncthreads();
        for (int i = tid; i < 32 * 128; i += 256) {
            int r = i >> 7, c = i & 127;
            Ws[r][c] = Wr[(size_t)(hc + r) * DIN + kbase + c];
        }
        __syncthreads();
        #pragma unroll 8
        for (int hh = 0; hh < 32; hh++) {
            float wv = Ws[hh][kk];
            #pragma unroll
            for (int i = 0; i < 8; i++)
                acc[i] += cn[grp * 8 + i][hc + hh] * wv;
        }
    }
    #pragma unroll
    for (int i = 0; i < 8; i++)
        g_d[(grp * 8 + i) * DIN + kbase + kk] = acc[i];
}

// ============================================================
// Kernel 2: ||z||^2 via bf16 mma, 128 threads (4 warps), warp tile
// 64x64 (fragment-byte relief, same as expert). 2-stage pipelined.
// Per-element mma chains and epilogue order unchanged -> g_n2p
// bit-identical to the proven version.
// ============================================================
__global__ __launch_bounds__(128, 2) void zn_kernel(
    const float* __restrict__ X, const float* __restrict__ Wr) {
    __shared__ unsigned As[2][128][12];
    __shared__ unsigned Bs[2][128][12];

    int tid = threadIdx.x;
    int m0 = blockIdx.y * 128;
    int n0 = blockIdx.x * 128;
    int wid = tid >> 5, lane = tid & 31;
    int wm = wid >> 1, wn = wid & 1;
    int g = lane >> 2, t = lane & 3;

    const float* aptr[4];
    const float* bptr[4];
    int rowL[4], c4L[4];
    #pragma unroll
    for (int i = 0; i < 4; i++) {
        int idx = tid + i * 128;
        rowL[i] = idx >> 2;
        c4L[i] = idx & 3;
        aptr[i] = X  + (size_t)(m0 + rowL[i]) * DIN + c4L[i] * 4;
        bptr[i] = Wr + (size_t)(n0 + rowL[i]) * DIN + c4L[i] * 4;
    }

    float acc[4][8][4];
    #pragma unroll
    for (int i = 0; i < 4; i++)
        #pragma unroll
        for (int j = 0; j < 8; j++)
            #pragma unroll
            for (int q = 0; q < 4; q++) acc[i][j][q] = 0.f;

    float4 av[4], bv[4];
    #pragma unroll
    for (int i = 0; i < 4; i++) {
        av[i] = *(const float4*)aptr[i];
        bv[i] = *(const float4*)bptr[i];
    }
    #pragma unroll
    for (int i = 0; i < 4; i++) {
        As[0][rowL[i]][c4L[i] * 2 + 0] = pack_bf16(av[i].x, av[i].y);
        As[0][rowL[i]][c4L[i] * 2 + 1] = pack_bf16(av[i].z, av[i].w);
        Bs[0][rowL[i]][c4L[i] * 2 + 0] = pack_bf16(bv[i].x, bv[i].y);
        Bs[0][rowL[i]][c4L[i] * 2 + 1] = pack_bf16(bv[i].z, bv[i].w);
    }
    __syncthreads();

    int cur = 0;
    for (int k0 = 0; k0 < DIN; k0 += 16) {
        bool nxt = (k0 + 16) < DIN;
        if (nxt) {
            #pragma unroll
            for (int i = 0; i < 4; i++) {
                av[i] = *(const float4*)(aptr[i] + k0 + 16);
                bv[i] = *(const float4*)(bptr[i] + k0 + 16);
            }
        }
        {
            unsigned a[4][4], b[8][2];
            #pragma unroll
            for (int mt = 0; mt < 4; mt++) {
                int rm = wm * 64 + mt * 16 + g;
                a[mt][0] = As[cur][rm][t];
                a[mt][1] = As[cur][rm + 8][t];
                a[mt][2] = As[cur][rm][t + 4];
                a[mt][3] = As[cur][rm + 8][t + 4];
            }
            #pragma unroll
            for (int nt = 0; nt < 8; nt++) {
                int rn = wn * 64 + nt * 8 + g;
                b[nt][0] = Bs[cur][rn][t];
                b[nt][1] = Bs[cur][rn][t + 4];
            }
            #pragma unroll
            for (int mt = 0; mt < 4; mt++)
                #pragma unroll
                for (int nt = 0; nt < 8; nt++)
                    mma_bf16(acc[mt][nt], a[mt], b[nt]);
        }
        if (nxt) {
            int st = cur ^ 1;
            #pragma unroll
            for (int i = 0; i < 4; i++) {
                As[st][rowL[i]][c4L[i] * 2 + 0] = pack_bf16(av[i].x, av[i].y);
                As[st][rowL[i]][c4L[i] * 2 + 1] = pack_bf16(av[i].z, av[i].w);
                Bs[st][rowL[i]][c4L[i] * 2 + 0] = pack_bf16(bv[i].x, bv[i].y);
                Bs[st][rowL[i]][c4L[i] * 2 + 1] = pack_bf16(bv[i].z, bv[i].w);
            }
        }
        __syncthreads();
        cur ^= 1;
    }

    int p = blockIdx.x * 2 + wn;
    #pragma unroll
    for (int mt = 0; mt < 4; mt++) {
        float s0 = 0.f, s1 = 0.f;
        #pragma unroll
        for (int nt = 0; nt < 8; nt++) {
            s0 += acc[mt][nt][0] * acc[mt][nt][0] + acc[mt][nt][1] * acc[mt][nt][1];
            s1 += acc[mt][nt][2] * acc[mt][nt][2] + acc[mt][nt][3] * acc[mt][nt][3];
        }
        s0 += __shfl_xor_sync(0xffffffffu, s0, 1);
        s0 += __shfl_xor_sync(0xffffffffu, s0, 2);
        s1 += __shfl_xor_sync(0xffffffffu, s1, 1);
        s1 += __shfl_xor_sync(0xffffffffu, s1, 2);
        if (t == 0) {
            int r = m0 + wm * 64 + mt * 16 + g;
            g_n2p[p][r] = s0;
            g_n2p[p][r + 8] = s1;
        }
    }
}

// ============================================================
// Kernel 3: fast routing, 2 tokens per warp (VERBATIM R10 winner)
// ============================================================
__global__ __launch_bounds__(256) void lroute_fast(
    const float* __restrict__ X, const float* __restrict__ temp) {
    __shared__ float ds[16][512];
    int tid = threadIdx.x, lane = tid & 31, w = tid >> 5;
    int tbase = blockIdx.x * 16 + w * 2;
    const float* xr0 = X + (size_t)tbase * DIN;

    float acc[2][16];
    #pragma unroll
    for (int q = 0; q < 2; q++)
        #pragma unroll
        for (int n = 0; n < 16; n++) acc[q][n] = 0.f;

    for (int c = 0; c < 4; c++) {
        __syncthreads();
        for (int i = tid; i < 16 * 128; i += 256) {
            int n = i >> 7, j = i & 127;
            *(float4*)&ds[n][j * 4] = *(const float4*)&g_d[n * DIN + c * 512 + j * 4];
        }
        __syncthreads();
        #pragma unroll
        for (int it = 0; it < 4; it++) {
            int k4 = it * 32 + lane;
            float4 xv0 = *(const float4*)&xr0[c * 512 + k4 * 4];
            float4 xv1 = *(const float4*)&xr0[DIN + c * 512 + k4 * 4];
            #pragma unroll
            for (int n = 0; n < 16; n++) {
                float4 dv = *(const float4*)&ds[n][k4 * 4];
                acc[0][n] += xv0.x * dv.x + xv0.y * dv.y + xv0.z * dv.z + xv0.w * dv.w;
                acc[1][n] += xv1.x * dv.x + xv1.y * dv.y + xv1.z * dv.z + xv1.w * dv.w;
            }
        }
    }
    #pragma unroll
    for (int o = 16; o; o >>= 1)
        #pragma unroll
        for (int q = 0; q < 2; q++)
            #pragma unroll
            for (int n = 0; n < 16; n++)
                acc[q][n] += __shfl_xor_sync(0xffffffffu, acc[q][n], o);

    if (lane < 2) {
        int q = lane;
        int t = tbase + q;
        float u[16];
        #pragma unroll
        for (int n = 0; n < 16; n++) u[n] = acc[q][n];
        float S = 0.f;
        #pragma unroll
        for (int n = 0; n < 16; n++) S = fmaxf(S, fabsf(u[n]));
        float v5[5];
        int i5[5];
        bool used[16];
        #pragma unroll
        for (int n = 0; n < 16; n++) used[n] = false;
        #pragma unroll
        for (int r = 0; r < 5; r++) {
            int bi = 0;
            float bv = -1e30f;
            #pragma unroll
            for (int n = 0; n < 16; n++)
                if (!used[n] && u[n] > bv) { bv = u[n]; bi = n; }
            used[bi] = true;
            v5[r] = bv;
            i5[r] = bi;
        }
        float tau = 1e-4f * S + 1e-12f;
        bool safe = (v5[0] - v5[1] > tau) && (v5[1] - v5[2] > tau) &&
                    (v5[2] - v5[3] > tau) && (v5[3] - v5[4] > tau);
        if (!safe) {
            int p = atomicAdd(&g_nflag, 1);
            g_flag[p] = t;
        } else {
            float n2 = g_n2p[0][t] + g_n2p[1][t] + g_n2p[2][t] + g_n2p[3][t];
            float inv = 1.0f / fmaxf(sqrtf(n2), 1e-12f);
            float sc = inv * 0.0625f * expf(temp[0]);
            float lg[16];
            float mx = -1e30f;
            #pragma unroll
            for (int n = 0; n < 16; n++) {
                lg[n] = u[n] * sc;
                mx = fmaxf(mx, lg[n]);
            }
            float sum = 0.f;
            #pragma unroll
            for (int n = 0; n < 16; n++) {
                lg[n] = expf(lg[n] - mx);
                sum += lg[n];
            }
            float isum = 1.0f / sum;
            #pragma unroll
            for (int k = 0; k < KSEL; k++) {
                int bi = i5[k];
                g_prob[t * KSEL + k] = lg[bi] * isum;
                int pos = atomicAdd(&g_cnt[bi], 1);
                g_list[bi * TOK + pos] = (t << 2) | k;
            }
        }
    }
}

// ============================================================
// Kernel 4: exact fallback for flagged tokens (bit-identical R1 chain).
// ============================================================
__global__ __launch_bounds__(256) void fallback_kernel(
    const float* __restrict__ X, const float* __restrict__ Wr,
    const float* __restrict__ temp) {
    __shared__ float xs[DIN];
    __shared__ float Wt[256][36];
    __shared__ float zs[256];
    __shared__ float red[8];
    __shared__ float slog[16];

    int nf = g_nflag;
    int tid = threadIdx.x, lane = tid & 31, w = tid >> 5;

    for (int fi = blockIdx.x; fi < nf; fi += gridDim.x) {
        int t = g_flag[fi];
        for (int i = tid; i < DIN / 4; i += 256)
            *(float4*)&xs[i * 4] = *(const float4*)&X[(size_t)t * DIN + i * 4];
        __syncthreads();
        float acc = 0.f;
        for (int k0 = 0; k0 < DIN; k0 += 32) {
            __syncthreads();
            for (int i = tid; i < 256 * 8; i += 256) {
                int r = i >> 3, c4 = i & 7;
                *(float4*)&Wt[r][c4 * 4] =
                    *(const float4*)&Wr[(size_t)r * DIN + k0 + c4 * 4];
            }
            __syncthreads();
            #pragma unroll
            for (int kk = 0; kk < 32; kk++)
                acc = __fmaf_rn(xs[k0 + kk], Wt[tid][kk], acc);
        }
        __syncthreads();
        float z = acc;
        zs[tid] = z;
        float s = z * z;
        #pragma unroll
        for (int o = 16; o; o >>= 1) s += __shfl_xor_sync(0xffffffffu, s, o);
        if (lane == 0) red[w] = s;
        __syncthreads();
        float tot = 0.f;
        #pragma unroll
        for (int i = 0; i < 8; i++) tot += red[i];
        float inv = 1.0f / fmaxf(sqrtf(tot), 1e-12f);

        for (int n = w; n < NHEAD; n += 8) {
            float p = 0.f;
            for (int i = lane; i < HIDN; i += 32) p += zs[i] * g_cnorm[n * HIDN + i];
            #pragma unroll
            for (int o = 16; o; o >>= 1) p += __shfl_xor_sync(0xffffffffu, p, o);
            if (lane == 0) slog[n] = p;
        }
        __syncthreads();

        if (tid == 0) {
            float sc = inv * 0.0625f * expf(temp[0]);
            float lg[16];
            float mx = -1e30f;
            #pragma unroll
            for (int n = 0; n < NHEAD; n++) {
                lg[n] = slog[n] * sc;
                mx = fmaxf(mx, lg[n]);
            }
            float sum = 0.f;
            #pragma unroll
            for (int n = 0; n < NHEAD; n++) {
                lg[n] = expf(lg[n] - mx);
                sum += lg[n];
            }
            float isum = 1.0f / sum;
            bool used[16];
            #pragma unroll
            for (int n = 0; n < NHEAD; n++) used[n] = false;
            for (int k = 0; k < KSEL; k++) {
                int bi = 0;
                float bv = -1e30f;
                #pragma unroll
                for (int n = 0; n < NHEAD; n++) {
                    if (!used[n] && lg[n] > bv) { bv = lg[n]; bi = n; }
                }
                used[bi] = true;
                g_prob[t * KSEL + k] = bv * isum;
                int pos = atomicAdd(&g_cnt[bi], 1);
                g_list[bi * TOK + pos] = (t << 2) | k;
            }
        }
        __syncthreads();
    }
}

// ============================================================
// Kernel 5: grouped expert GEMM, tf32 mma, 2-stage pipelined.
// 128 threads (4 warps), warp tile 64x64 (VERBATIM R14 winner).
// ============================================================
__global__ __launch_bounds__(128, 2) void gemm_expert_mma(
    const float* __restrict__ X, const float* __restrict__ W,
    const float* __restrict__ bias, float* __restrict__ out) {
    int h = blockIdx.y;
    int cnt = g_cnt[h];
    int base = blockIdx.x * 128;
    if (base >= cnt) return;

    __shared__ unsigned As[2][128][20];
    __shared__ unsigned Bs[2][128][20];
    __shared__ int   s_ent[128];
    __shared__ float s_prob[128];
    __shared__ float s_bias[128];

    int tid = threadIdx.x;
    {
        int r = base + tid;
        int rr = (r < cnt) ? r : (cnt - 1);
        int ent = g_list[h * TOK + rr];
        s_ent[tid] = ent;
        s_prob[tid] = g_prob[ent];
        s_bias[tid] = bias[h * HDIM + tid];
    }
    __syncthreads();

    const float* Wh = W + (size_t)h * HDIM * DIN;
    const float* aptr[4];
    const float* bptr[4];
    int rowL[4], c4L[4];
    #pragma unroll
    for (int i = 0; i < 4; i++) {
        int idx = tid + i * 128;
        rowL[i] = idx >> 2;
        c4L[i] = idx & 3;
        int tok = s_ent[rowL[i]] >> 2;
        aptr[i] = X  + (size_t)tok * DIN + c4L[i] * 4;
        bptr[i] = Wh + (size_t)rowL[i] * DIN + c4L[i] * 4;
    }

    int wid = tid >> 5, lane = tid & 31;
    int wm = wid >> 1, wn = wid & 1;
    int g = lane >> 2, t = lane & 3;

    float acc[4][8][4];
    #pragma unroll
    for (int i = 0; i < 4; i++)
        #pragma unroll
        for (int j = 0; j < 8; j++)
            #pragma unroll
            for (int q = 0; q < 4; q++) acc[i][j][q] = 0.f;

    float4 av[4], bv[4];
    #pragma unroll
    for (int i = 0; i < 4; i++) {
        av[i] = *(const float4*)aptr[i];
        bv[i] = *(const float4*)bptr[i];
    }
    #pragma unroll
    for (int i = 0; i < 4; i++) {
        uint4 u;
        u.x = f2tf32(av[i].x); u.y = f2tf32(av[i].y);
        u.z = f2tf32(av[i].z); u.w = f2tf32(av[i].w);
        *(uint4*)&As[0][rowL[i]][c4L[i] * 4] = u;
        u.x = f2tf32(bv[i].x); u.y = f2tf32(bv[i].y);
        u.z = f2tf32(bv[i].z); u.w = f2tf32(bv[i].w);
        *(uint4*)&Bs[0][rowL[i]][c4L[i] * 4] = u;
    }
    __syncthreads();

    int cur = 0;
    for (int k0 = 0; k0 < DIN; k0 += 16) {
        bool nxt = (k0 + 16) < DIN;
        if (nxt) {
            #pragma unroll
            for (int i = 0; i < 4; i++) {
                av[i] = *(const float4*)(aptr[i] + k0 + 16);
                bv[i] = *(const float4*)(bptr[i] + k0 + 16);
            }
        }
        #pragma unroll
        for (int s = 0; s < 2; s++) {
            unsigned a[4][4], b[8][2];
            int kc = s * 8 + t;
            #pragma unroll
            for (int mt = 0; mt < 4; mt++) {
                int rm = wm * 64 + mt * 16 + g;
                a[mt][0] = As[cur][rm][kc];
                a[mt][1] = As[cur][rm + 8][kc];
                a[mt][2] = As[cur][rm][kc + 4];
                a[mt][3] = As[cur][rm + 8][kc + 4];
            }
            #pragma unroll
            for (int nt = 0; nt < 8; nt++) {
                int rn = wn * 64 + nt * 8 + g;
                b[nt][0] = Bs[cur][rn][kc];
                b[nt][1] = Bs[cur][rn][kc + 4];
            }
            #pragma unroll
            for (int mt = 0; mt < 4; mt++)
                #pragma unroll
                for (int nt = 0; nt < 8; nt++)
                    mma_tf32(acc[mt][nt], a[mt], b[nt]);
        }
        if (nxt) {
            int st = cur ^ 1;
            #pragma unroll
            for (int i = 0; i < 4; i++) {
                uint4 u;
                u.x = f2tf32(av[i].x); u.y = f2tf32(av[i].y);
                u.z = f2tf32(av[i].z); u.w = f2tf32(av[i].w);
                *(uint4*)&As[st][rowL[i]][c4L[i] * 4] = u;
                u.x = f2tf32(bv[i].x); u.y = f2tf32(bv[i].y);
                u.z = f2tf32(bv[i].z); u.w = f2tf32(bv[i].w);
                *(uint4*)&Bs[st][rowL[i]][c4L[i] * 4] = u;
            }
        }
        __syncthreads();
        cur ^= 1;
    }

    #pragma unroll
    for (int mt = 0; mt < 4; mt++)
        #pragma unroll
        for (int half = 0; half < 2; half++) {
            int r = wm * 64 + mt * 16 + g + half * 8;
            if (base + r < cnt) {
                int ent = s_ent[r];
                int tok = ent >> 2, slot = ent & 3;
                float p = s_prob[r];
                float* op = out + (size_t)tok * OUTW + slot * HDIM;
                #pragma unroll
                for (int nt = 0; nt < 8; nt++) {
                    int col = wn * 64 + nt * 8 + 2 * t;
                    float2 v;
                    v.x = (acc[mt][nt][half * 2 + 0] + s_bias[col]) * p;
                    v.y = (acc[mt][nt][half * 2 + 1] + s_bias[col + 1]) * p;
                    *(float2*)&op[col] = v;
                }
            }
        }
}

// ============================================================
extern "C" void kernel_launch(void* const* d_in, const int* in_sizes, int n_in,
                              void* d_out, int out_size) {
    const float* x    = (const float*)d_in[0];  // [4,4096,2048]
    const float* rw   = (const float*)d_in[1];  // [256,2048]
    const float* cent = (const float*)d_in[2];  // [16,256]
    const float* temp = (const float*)d_in[3];  // [1]
    const float* w    = (const float*)d_in[4];  // [2048,2048]
    const float* b    = (const float*)d_in[5];  // [2048]
    float* out = (float*)d_out;                 // [4,4096,512]

    prep_kernel<<<1, 256>>>(cent);
    dprep_kernel<<<16, 256>>>(rw);
    zn_kernel<<<dim3(2, 128), 128>>>(x, rw);
    lroute_fast<<<1024, 256>>>(x, temp);
    fallback_kernel<<<128, 256>>>(x, rw, temp);
    gemm_expert_mma<<<dim3(128, 16), 128>>>(x, w, b, out);
}